// round 1
// baseline (speedup 1.0000x reference)
#include <cuda_runtime.h>
#include <cuda_bf16.h>
#include <math.h>

// Problem constants
#define BQ 64            // batch (query rows)
#define MB 256           // memory bank entries
#define DLL 524288LL     // feature dim K
#define TD 8             // K-rows per smem tile
#define NCHUNK 296       // split-K chunks = 2 CTAs/SM * 148 SMs (one wave)
#define NTILES 65536     // DLL / TD
#define SDIM 2048        // style dim

// Static scratch (no allocation allowed in kernel_launch)
__device__ float g_psim[NCHUNK * BQ * MB];   // [chunk][b][m] partial dot products
__device__ float g_pnorm[NCHUNK * MB];       // [chunk][m]   partial column norms^2

// ---- packed f32x2 helpers (sm_103a) ----
__device__ __forceinline__ unsigned long long pack2(float x, float y) {
    unsigned long long r;
    asm("mov.b64 %0, {%1, %2};" : "=l"(r) : "f"(x), "f"(y));
    return r;
}
__device__ __forceinline__ void fma2(unsigned long long& d,
                                     unsigned long long a,
                                     unsigned long long b) {
    asm("fma.rn.f32x2 %0, %1, %2, %0;" : "+l"(d) : "l"(a), "l"(b));
}
__device__ __forceinline__ float2 unpack2(unsigned long long v) {
    float2 r;
    asm("mov.b64 {%0, %1}, %2;" : "=f"(r.x), "=f"(r.y) : "l"(v));
    return r;
}

// =====================================================================
// Kernel 1: split-K fused GEMM + column-norm partial reduction.
//   sim[b,m]  = sum_d content[b*D+d] * bank[d*M+m]
//   norm2[m]  = sum_d bank[d*M+m]^2
// grid = NCHUNK blocks, 256 threads. Thread (tb=t/32, tm=t%32) owns
// b in [tb*8, tb*8+8) x m in [tm*8, tm*8+8)  -> 32 f32x2 accumulators.
// =====================================================================
__global__ __launch_bounds__(256, 2)
void sim_norm_kernel(const float* __restrict__ content,
                     const float* __restrict__ bank) {
    __shared__ float bk_s[TD * MB];   // 8 KB: bank tile [i][m]
    __shared__ float cs_s[BQ * TD];   // 2 KB: content tile [b][i]

    const int tid = threadIdx.x;
    const int tb  = tid >> 5;         // 0..7  (b group)
    const int tm  = tid & 31;         // 0..31 (m group)

    // tile range for this chunk (all tiles full TD rows)
    const int tbase = NTILES / NCHUNK;            // 221
    const int trem  = NTILES % NCHUNK;            // 120
    const int extra = (blockIdx.x < trem) ? 1 : 0;
    const int t0 = blockIdx.x * tbase + (blockIdx.x < trem ? blockIdx.x : trem);
    const int nt = tbase + extra;

    unsigned long long acc[8][4];
    #pragma unroll
    for (int j = 0; j < 8; ++j)
        #pragma unroll
        for (int p = 0; p < 4; ++p) acc[j][p] = 0ULL;
    unsigned long long nrm[4] = {0ULL, 0ULL, 0ULL, 0ULL};

    for (int t = 0; t < nt; ++t) {
        const long long d0 = (long long)(t0 + t) * TD;

        // --- stage bank tile: TD*MB = 2048 floats, fully coalesced ---
        {
            const float4* src = (const float4*)(bank + d0 * MB);
            float4* dst = (float4*)bk_s;
            dst[tid]       = src[tid];
            dst[tid + 256] = src[tid + 256];
        }
        // --- stage content tile: 64 rows x 8 floats ---
        if (tid < 128) {
            const int b = tid >> 1, half = tid & 1;
            const float4 v = *(const float4*)(content + (long long)b * DLL + d0 + half * 4);
            ((float4*)cs_s)[tid] = v;   // cs_s[b*8 + half*4 ..]
        }
        __syncthreads();

        // --- compute: process i in groups of 4 so cs reads are float4 ---
        #pragma unroll
        for (int i4 = 0; i4 < TD; i4 += 4) {
            // bank pairs for 4 consecutive i: [ii][p] f32x2
            unsigned long long bp[4][4];
            #pragma unroll
            for (int ii = 0; ii < 4; ++ii) {
                const ulonglong2 v0 = *(const ulonglong2*)&bk_s[(i4 + ii) * MB + tm * 8];
                const ulonglong2 v1 = *(const ulonglong2*)&bk_s[(i4 + ii) * MB + tm * 8 + 4];
                bp[ii][0] = v0.x; bp[ii][1] = v0.y;
                bp[ii][2] = v1.x; bp[ii][3] = v1.y;
            }
            // norm^2 accumulation (one b-group is enough; values identical across tb)
            if (tb == 0) {
                #pragma unroll
                for (int ii = 0; ii < 4; ++ii)
                    #pragma unroll
                    for (int p = 0; p < 4; ++p)
                        fma2(nrm[p], bp[ii][p], bp[ii][p]);
            }
            #pragma unroll
            for (int j = 0; j < 8; ++j) {
                const float4 cv = *(const float4*)&cs_s[(tb * 8 + j) * TD + i4];
                const float cf[4] = {cv.x, cv.y, cv.z, cv.w};
                #pragma unroll
                for (int ii = 0; ii < 4; ++ii) {
                    const unsigned long long cc = pack2(cf[ii], cf[ii]);
                    #pragma unroll
                    for (int p = 0; p < 4; ++p)
                        fma2(acc[j][p], cc, bp[ii][p]);
                }
            }
        }
        __syncthreads();
    }

    // --- write partials ---
    float* ps = g_psim + (size_t)blockIdx.x * (BQ * MB);
    #pragma unroll
    for (int j = 0; j < 8; ++j) {
        const int row = tb * 8 + j;
        #pragma unroll
        for (int p = 0; p < 4; ++p) {
            *(float2*)&ps[row * MB + tm * 8 + p * 2] = unpack2(acc[j][p]);
        }
    }
    if (tb == 0) {
        float* pn = g_pnorm + (size_t)blockIdx.x * MB;
        #pragma unroll
        for (int p = 0; p < 4; ++p)
            *(float2*)&pn[tm * 8 + p * 2] = unpack2(nrm[p]);
    }
}

// =====================================================================
// Kernel 2: reduce partials -> score -> argmax (first index wins) -> gather.
// grid = 64 (one per b), 1024 threads: (q = tid>>8) sums a quarter of chunks.
// =====================================================================
__global__ __launch_bounds__(1024)
void argmax_gather_kernel(const float* __restrict__ style,
                          float* __restrict__ out) {
    const int b   = blockIdx.x;
    const int tid = threadIdx.x;
    const int m   = tid & 255;
    const int q   = tid >> 8;            // 0..3
    const int CPQ = NCHUNK / 4;          // 74

    float sim = 0.f, n2 = 0.f;
    const int c0 = q * CPQ;
    for (int c = c0; c < c0 + CPQ; ++c) {
        sim += g_psim[(size_t)c * (BQ * MB) + b * MB + m];
        n2  += g_pnorm[(size_t)c * MB + m];
    }

    __shared__ float s_sim[4][256];
    __shared__ float s_n2[4][256];
    s_sim[q][m] = sim;
    s_n2[q][m]  = n2;
    __syncthreads();

    __shared__ float s_val[256];
    __shared__ int   s_idx[256];
    if (q == 0) {
        const float st = s_sim[0][m] + s_sim[1][m] + s_sim[2][m] + s_sim[3][m];
        const float nt = s_n2[0][m]  + s_n2[1][m]  + s_n2[2][m]  + s_n2[3][m];
        const float norm = fmaxf(sqrtf(nt), 1e-12f);
        s_val[m] = st / norm;
        s_idx[m] = m;
    }
    __syncthreads();

    // tree argmax, first-occurrence tie-break (smaller index wins on equal)
    #pragma unroll
    for (int s = 128; s > 0; s >>= 1) {
        if (tid < s) {
            const float v1 = s_val[tid + s], v0 = s_val[tid];
            const int   i1 = s_idx[tid + s], i0 = s_idx[tid];
            if (v1 > v0 || (v1 == v0 && i1 < i0)) {
                s_val[tid] = v1;
                s_idx[tid] = i1;
            }
        }
        __syncthreads();
    }
    const int idx = s_idx[0];

    // gather style row: 2048 floats, 1024 threads x float2
    const float2* src = (const float2*)(style + (size_t)idx * SDIM);
    float2* dst = (float2*)(out + (size_t)b * SDIM);
    dst[tid] = src[tid];
}

extern "C" void kernel_launch(void* const* d_in, const int* in_sizes, int n_in,
                              void* d_out, int out_size) {
    const float* content = (const float*)d_in[0];   // [64, 512, 32, 32]
    const float* bank    = (const float*)d_in[1];   // [256, 524288]
    const float* style   = (const float*)d_in[2];   // [256, 2048]
    float* out = (float*)d_out;                     // [64, 2048]

    sim_norm_kernel<<<NCHUNK, 256>>>(content, bank);
    argmax_gather_kernel<<<BQ, 1024>>>(style, out);
}

// round 2
// speedup vs baseline: 1.0048x; 1.0048x over previous
#include <cuda_runtime.h>
#include <cuda_bf16.h>
#include <math.h>

// Problem constants
#define BQ 64            // batch (query rows)
#define MB 256           // memory bank entries
#define DLL 524288LL     // feature dim K
#define TD 8             // K-rows per smem tile
#define NCHUNK 296       // split-K chunks = 2 CTAs/SM * 148 SMs (one wave)
#define NTILES 65536     // DLL / TD
#define SDIM 2048        // style dim

// Static scratch (no allocation allowed in kernel_launch)
__device__ float g_psim[NCHUNK * BQ * MB];   // [chunk][b][m] partial dot products
__device__ float g_pnorm[NCHUNK * MB];       // [chunk][m]   partial column norms^2

// ---- packed f32x2 helpers (sm_103a) ----
__device__ __forceinline__ unsigned long long pack2(float x, float y) {
    unsigned long long r;
    asm("mov.b64 %0, {%1, %2};" : "=l"(r) : "f"(x), "f"(y));
    return r;
}
__device__ __forceinline__ void fma2(unsigned long long& d,
                                     unsigned long long a,
                                     unsigned long long b) {
    asm("fma.rn.f32x2 %0, %1, %2, %0;" : "+l"(d) : "l"(a), "l"(b));
}
__device__ __forceinline__ float2 unpack2(unsigned long long v) {
    float2 r;
    asm("mov.b64 {%0, %1}, %2;" : "=f"(r.x), "=f"(r.y) : "l"(v));
    return r;
}

// =====================================================================
// Kernel 1: split-K fused GEMM + column-norm partial reduction.
//   sim[b,m]  = sum_d content[b*D+d] * bank[d*M+m]
//   norm2[m]  = sum_d bank[d*M+m]^2
// grid = NCHUNK blocks, 256 threads. Thread (tb=t/32, tm=t%32) owns
// b in [tb*8, tb*8+8) x m in [tm*8, tm*8+8)  -> 32 f32x2 accumulators.
// =====================================================================
__global__ __launch_bounds__(256, 2)
void sim_norm_kernel(const float* __restrict__ content,
                     const float* __restrict__ bank) {
    __shared__ float bk_s[TD * MB];   // 8 KB: bank tile [i][m]
    __shared__ float cs_s[BQ * TD];   // 2 KB: content tile [b][i]

    const int tid = threadIdx.x;
    const int tb  = tid >> 5;         // 0..7  (b group)
    const int tm  = tid & 31;         // 0..31 (m group)

    // tile range for this chunk (all tiles full TD rows)
    const int tbase = NTILES / NCHUNK;            // 221
    const int trem  = NTILES % NCHUNK;            // 120
    const int extra = (blockIdx.x < trem) ? 1 : 0;
    const int t0 = blockIdx.x * tbase + (blockIdx.x < trem ? blockIdx.x : trem);
    const int nt = tbase + extra;

    unsigned long long acc[8][4];
    #pragma unroll
    for (int j = 0; j < 8; ++j)
        #pragma unroll
        for (int p = 0; p < 4; ++p) acc[j][p] = 0ULL;
    unsigned long long nrm[4] = {0ULL, 0ULL, 0ULL, 0ULL};

    for (int t = 0; t < nt; ++t) {
        const long long d0 = (long long)(t0 + t) * TD;

        // --- stage bank tile: TD*MB = 2048 floats, fully coalesced ---
        {
            const float4* src = (const float4*)(bank + d0 * MB);
            float4* dst = (float4*)bk_s;
            dst[tid]       = src[tid];
            dst[tid + 256] = src[tid + 256];
        }
        // --- stage content tile: 64 rows x 8 floats ---
        if (tid < 128) {
            const int b = tid >> 1, half = tid & 1;
            const float4 v = *(const float4*)(content + (long long)b * DLL + d0 + half * 4);
            ((float4*)cs_s)[tid] = v;   // cs_s[b*8 + half*4 ..]
        }
        __syncthreads();

        // --- compute: process i in groups of 4 so cs reads are float4 ---
        #pragma unroll
        for (int i4 = 0; i4 < TD; i4 += 4) {
            // bank pairs for 4 consecutive i: [ii][p] f32x2
            unsigned long long bp[4][4];
            #pragma unroll
            for (int ii = 0; ii < 4; ++ii) {
                const ulonglong2 v0 = *(const ulonglong2*)&bk_s[(i4 + ii) * MB + tm * 8];
                const ulonglong2 v1 = *(const ulonglong2*)&bk_s[(i4 + ii) * MB + tm * 8 + 4];
                bp[ii][0] = v0.x; bp[ii][1] = v0.y;
                bp[ii][2] = v1.x; bp[ii][3] = v1.y;
            }
            // norm^2 accumulation (one b-group is enough; values identical across tb)
            if (tb == 0) {
                #pragma unroll
                for (int ii = 0; ii < 4; ++ii)
                    #pragma unroll
                    for (int p = 0; p < 4; ++p)
                        fma2(nrm[p], bp[ii][p], bp[ii][p]);
            }
            #pragma unroll
            for (int j = 0; j < 8; ++j) {
                const float4 cv = *(const float4*)&cs_s[(tb * 8 + j) * TD + i4];
                const float cf[4] = {cv.x, cv.y, cv.z, cv.w};
                #pragma unroll
                for (int ii = 0; ii < 4; ++ii) {
                    const unsigned long long cc = pack2(cf[ii], cf[ii]);
                    #pragma unroll
                    for (int p = 0; p < 4; ++p)
                        fma2(acc[j][p], cc, bp[ii][p]);
                }
            }
        }
        __syncthreads();
    }

    // --- write partials ---
    float* ps = g_psim + (size_t)blockIdx.x * (BQ * MB);
    #pragma unroll
    for (int j = 0; j < 8; ++j) {
        const int row = tb * 8 + j;
        #pragma unroll
        for (int p = 0; p < 4; ++p) {
            *(float2*)&ps[row * MB + tm * 8 + p * 2] = unpack2(acc[j][p]);
        }
    }
    if (tb == 0) {
        float* pn = g_pnorm + (size_t)blockIdx.x * MB;
        #pragma unroll
        for (int p = 0; p < 4; ++p)
            *(float2*)&pn[tm * 8 + p * 2] = unpack2(nrm[p]);
    }
}

// =====================================================================
// Kernel 2: reduce partials -> score -> argmax (first index wins) -> gather.
// grid = 64 (one per b), 1024 threads: (q = tid>>8) sums a quarter of chunks.
// =====================================================================
__global__ __launch_bounds__(1024)
void argmax_gather_kernel(const float* __restrict__ style,
                          float* __restrict__ out) {
    const int b   = blockIdx.x;
    const int tid = threadIdx.x;
    const int m   = tid & 255;
    const int q   = tid >> 8;            // 0..3
    const int CPQ = NCHUNK / 4;          // 74

    float sim = 0.f, n2 = 0.f;
    const int c0 = q * CPQ;
    for (int c = c0; c < c0 + CPQ; ++c) {
        sim += g_psim[(size_t)c * (BQ * MB) + b * MB + m];
        n2  += g_pnorm[(size_t)c * MB + m];
    }

    __shared__ float s_sim[4][256];
    __shared__ float s_n2[4][256];
    s_sim[q][m] = sim;
    s_n2[q][m]  = n2;
    __syncthreads();

    __shared__ float s_val[256];
    __shared__ int   s_idx[256];
    if (q == 0) {
        const float st = s_sim[0][m] + s_sim[1][m] + s_sim[2][m] + s_sim[3][m];
        const float nt = s_n2[0][m]  + s_n2[1][m]  + s_n2[2][m]  + s_n2[3][m];
        const float norm = fmaxf(sqrtf(nt), 1e-12f);
        s_val[m] = st / norm;
        s_idx[m] = m;
    }
    __syncthreads();

    // tree argmax, first-occurrence tie-break (smaller index wins on equal)
    #pragma unroll
    for (int s = 128; s > 0; s >>= 1) {
        if (tid < s) {
            const float v1 = s_val[tid + s], v0 = s_val[tid];
            const int   i1 = s_idx[tid + s], i0 = s_idx[tid];
            if (v1 > v0 || (v1 == v0 && i1 < i0)) {
                s_val[tid] = v1;
                s_idx[tid] = i1;
            }
        }
        __syncthreads();
    }
    const int idx = s_idx[0];

    // gather style row: 2048 floats, 1024 threads x float2
    const float2* src = (const float2*)(style + (size_t)idx * SDIM);
    float2* dst = (float2*)(out + (size_t)b * SDIM);
    dst[tid] = src[tid];
}

extern "C" void kernel_launch(void* const* d_in, const int* in_sizes, int n_in,
                              void* d_out, int out_size) {
    const float* content = (const float*)d_in[0];   // [64, 512, 32, 32]
    const float* bank    = (const float*)d_in[1];   // [256, 524288]
    const float* style   = (const float*)d_in[2];   // [256, 2048]
    float* out = (float*)d_out;                     // [64, 2048]

    sim_norm_kernel<<<NCHUNK, 256>>>(content, bank);
    argmax_gather_kernel<<<BQ, 1024>>>(style, out);
}

// round 4
// speedup vs baseline: 4.0084x; 3.9893x over previous
#include <cuda_runtime.h>
#include <cuda_bf16.h>
#include <cstdint>

// ---------------- problem constants ----------------
#define BQ 64            // batch (query rows / GEMM M)
#define MB 256           // memory bank entries  (GEMM N)
#define DLL 524288LL     // feature dim K
#define KT 32            // K per tile
#define NTT 16384        // DLL / KT
#define NCTA 152         // 1 CTA per SM on GB300
#define SDIM 2048        // style dim

// static scratch (no allocs allowed)
__device__ float g_psim[NCTA * BQ * MB];   // [cta][b][m]
__device__ float g_pnorm[NCTA * MB];       // [cta][m]

// ---------------- smem layout (bytes, per buffer) ----------------
// A (content) : [64 b][k pitch 40] bf16  -> 64*80  = 5120 B   (hi, lo)
// B (bank)    : [32 k][n pitch 264] bf16 -> 32*528 = 16896 B  (hi, lo)
#define A_HI 0u
#define A_LO 5120u
#define B_HI 10240u
#define B_LO 27136u
#define BUFB 44032u
#define SMEM_TOTAL (2u * BUFB)   // 88064

// ---------------- helpers ----------------
static __device__ __forceinline__ uint32_t smem_u32(const void* p) {
    uint32_t a;
    asm("{ .reg .u64 t; cvta.to.shared.u64 t, %1; cvt.u32.u64 %0, t; }"
        : "=r"(a) : "l"(p));
    return a;
}

static __device__ __forceinline__ void ldsm4(uint32_t* r, uint32_t addr) {
    asm volatile("ldmatrix.sync.aligned.m8n8.x4.shared.b16 {%0,%1,%2,%3}, [%4];"
                 : "=r"(r[0]), "=r"(r[1]), "=r"(r[2]), "=r"(r[3]) : "r"(addr));
}
static __device__ __forceinline__ void ldsm4t(uint32_t* r, uint32_t addr) {
    asm volatile("ldmatrix.sync.aligned.m8n8.x4.trans.shared.b16 {%0,%1,%2,%3}, [%4];"
                 : "=r"(r[0]), "=r"(r[1]), "=r"(r[2]), "=r"(r[3]) : "r"(addr));
}
static __device__ __forceinline__ void mma16816(float* c, const uint32_t* a,
                                                const uint32_t* b) {
    asm volatile(
        "mma.sync.aligned.m16n8k16.row.col.f32.bf16.bf16.f32 "
        "{%0,%1,%2,%3}, {%4,%5,%6,%7}, {%8,%9}, {%0,%1,%2,%3};"
        : "+f"(c[0]), "+f"(c[1]), "+f"(c[2]), "+f"(c[3])
        : "r"(a[0]), "r"(a[1]), "r"(a[2]), "r"(a[3]), "r"(b[0]), "r"(b[1]));
}

// fp32x4 -> bf16 hi/lo pairs (hi = rn(bf16), lo = rn(bf16(residual)))
static __device__ __forceinline__ void cvt4(float4 v, uint2& hi, uint2& lo) {
    __nv_bfloat162 h0 = __floats2bfloat162_rn(v.x, v.y);
    __nv_bfloat162 h1 = __floats2bfloat162_rn(v.z, v.w);
    uint32_t u0 = *(uint32_t*)&h0;
    uint32_t u1 = *(uint32_t*)&h1;
    float rx = v.x - __uint_as_float(u0 << 16);
    float ry = v.y - __uint_as_float(u0 & 0xffff0000u);
    float rz = v.z - __uint_as_float(u1 << 16);
    float rw = v.w - __uint_as_float(u1 & 0xffff0000u);
    __nv_bfloat162 l0 = __floats2bfloat162_rn(rx, ry);
    __nv_bfloat162 l1 = __floats2bfloat162_rn(rz, rw);
    hi = make_uint2(u0, u1);
    lo = make_uint2(*(uint32_t*)&l0, *(uint32_t*)&l1);
}

// =====================================================================
// Kernel 1: split-K bf16x3 mma.sync GEMM + fused fp32->bf16 hi/lo
// conversion + column norm^2.  grid = NCTA, 256 threads (8 warps).
// Warp w owns output slab  b[0..64) x n[w*32, w*32+32).
// =====================================================================
__global__ void __launch_bounds__(256)
sim_mma_kernel(const float* __restrict__ content, const float* __restrict__ bank) {
    extern __shared__ char smem[];
    const uint32_t sbase = smem_u32(smem);
    const int tid  = threadIdx.x;
    const int lane = tid & 31;
    const int w    = tid >> 5;
    const int bid  = blockIdx.x;

    // tile range for this CTA
    const int tbase = NTT / NCTA;                 // 107
    const int trem  = NTT % NCTA;                 // 120
    const int t0 = bid * tbase + (bid < trem ? bid : trem);
    const int nt = tbase + (bid < trem ? 1 : 0);

    // per-thread load indices
    const int n4 = tid & 63;      // bank float4 column (n = 4*n4..)
    const int kq = tid >> 6;      // 0..3  (bank k-row = i*4 + kq)
    const int lr = lane & 15;     // ldmatrix row within 16
    const int lc = lane >> 4;     // ldmatrix 8-col group

    float acc[4][4][4];
    #pragma unroll
    for (int i = 0; i < 4; ++i)
        #pragma unroll
        for (int j = 0; j < 4; ++j)
            #pragma unroll
            for (int k = 0; k < 4; ++k) acc[i][j][k] = 0.f;
    float4 nrm = make_float4(0.f, 0.f, 0.f, 0.f);

    // register staging for the current tile's global data
    float4 bkreg[8];
    float4 ctreg[2];

    // prologue: load tile 0
    {
        const float4* bs = (const float4*)bank + (long long)t0 * KT * 64;
        #pragma unroll
        for (int i = 0; i < 8; ++i) bkreg[i] = bs[(i * 4 + kq) * 64 + n4];
        #pragma unroll
        for (int i = 0; i < 2; ++i) {
            const int idx = i * 256 + tid, b = idx >> 3, k4 = idx & 7;
            ctreg[i] = *(const float4*)(content + (long long)b * DLL +
                                        (long long)t0 * KT + k4 * 4);
        }
    }

    for (int t = 0; t < nt; ++t) {
        const int p = t & 1;
        char* buf = smem + (uint32_t)p * BUFB;

        // ---- convert + STS + norm^2 (bank) ----
        #pragma unroll
        for (int i = 0; i < 8; ++i) {
            uint2 hi, lo;
            cvt4(bkreg[i], hi, lo);
            const uint32_t off = (uint32_t)(i * 4 + kq) * 528u + (uint32_t)n4 * 8u;
            *(uint2*)(buf + B_HI + off) = hi;
            *(uint2*)(buf + B_LO + off) = lo;
            nrm.x = fmaf(bkreg[i].x, bkreg[i].x, nrm.x);
            nrm.y = fmaf(bkreg[i].y, bkreg[i].y, nrm.y);
            nrm.z = fmaf(bkreg[i].z, bkreg[i].z, nrm.z);
            nrm.w = fmaf(bkreg[i].w, bkreg[i].w, nrm.w);
        }
        // ---- convert + STS (content) ----
        #pragma unroll
        for (int i = 0; i < 2; ++i) {
            uint2 hi, lo;
            cvt4(ctreg[i], hi, lo);
            const int idx = i * 256 + tid, b = idx >> 3, k4 = idx & 7;
            const uint32_t off = (uint32_t)b * 80u + (uint32_t)k4 * 8u;
            *(uint2*)(buf + A_HI + off) = hi;
            *(uint2*)(buf + A_LO + off) = lo;
        }
        __syncthreads();

        // ---- prefetch next tile (LDG latency hidden behind MMA) ----
        if (t + 1 < nt) {
            const long long d0n = (long long)(t0 + t + 1) * KT;
            const float4* bs = (const float4*)bank + d0n * 64;
            #pragma unroll
            for (int i = 0; i < 8; ++i) bkreg[i] = bs[(i * 4 + kq) * 64 + n4];
            #pragma unroll
            for (int i = 0; i < 2; ++i) {
                const int idx = i * 256 + tid, b = idx >> 3, k4 = idx & 7;
                ctreg[i] = *(const float4*)(content + (long long)b * DLL + d0n + k4 * 4);
            }
        }

        // ---- MMA phase: 2 k-steps of 16, 48 mma each ----
        const uint32_t bb = sbase + (uint32_t)p * BUFB;
        #pragma unroll
        for (int kk = 0; kk < 2; ++kk) {
            uint32_t ah[4][4], al[4][4];
            #pragma unroll
            for (int fm = 0; fm < 4; ++fm) {
                const uint32_t aoff = (uint32_t)(fm * 16 + lr) * 80u +
                                      (uint32_t)(kk * 16 + lc * 8) * 2u;
                ldsm4(ah[fm], bb + A_HI + aoff);
                ldsm4(al[fm], bb + A_LO + aoff);
            }
            uint32_t bh[4][2], bl[4][2];
            #pragma unroll
            for (int g = 0; g < 2; ++g) {
                const uint32_t boff = (uint32_t)(kk * 16 + lr) * 528u +
                                      (uint32_t)(w * 32 + g * 16 + lc * 8) * 2u;
                uint32_t r[4];
                ldsm4t(r, bb + B_HI + boff);
                bh[g * 2][0] = r[0]; bh[g * 2][1] = r[1];
                bh[g * 2 + 1][0] = r[2]; bh[g * 2 + 1][1] = r[3];
                ldsm4t(r, bb + B_LO + boff);
                bl[g * 2][0] = r[0]; bl[g * 2][1] = r[1];
                bl[g * 2 + 1][0] = r[2]; bl[g * 2 + 1][1] = r[3];
            }
            #pragma unroll
            for (int fm = 0; fm < 4; ++fm)
                #pragma unroll
                for (int fn = 0; fn < 4; ++fn) {
                    mma16816(acc[fm][fn], ah[fm], bh[fn]);   // hi*hi
                    mma16816(acc[fm][fn], ah[fm], bl[fn]);   // hi*lo
                    mma16816(acc[fm][fn], al[fm], bh[fn]);   // lo*hi
                }
        }
    }
    __syncthreads();   // smem reuse below

    // ---- norm^2 reduce across the 4 k-quarters ----
    ((float4*)smem)[tid] = nrm;
    __syncthreads();
    if (tid < 64) {
        const float4* n = (const float4*)smem;
        float4 s0 = n[tid], s1 = n[tid + 64], s2 = n[tid + 128], s3 = n[tid + 192];
        float4 s = make_float4(s0.x + s1.x + s2.x + s3.x,
                               s0.y + s1.y + s2.y + s3.y,
                               s0.z + s1.z + s2.z + s3.z,
                               s0.w + s1.w + s2.w + s3.w);
        *(float4*)(g_pnorm + (size_t)bid * MB + tid * 4) = s;
    }

    // ---- psim write (fragment layout -> [b][n]) ----
    {
        float* ps = g_psim + (size_t)bid * (BQ * MB);
        const int gr = lane >> 2, c2 = (lane & 3) * 2;
        #pragma unroll
        for (int fm = 0; fm < 4; ++fm)
            #pragma unroll
            for (int fn = 0; fn < 4; ++fn) {
                const int b0 = fm * 16 + gr;
                const int n  = w * 32 + fn * 8 + c2;
                *(float2*)&ps[b0 * MB + n] =
                    make_float2(acc[fm][fn][0], acc[fm][fn][1]);
                *(float2*)&ps[(b0 + 8) * MB + n] =
                    make_float2(acc[fm][fn][2], acc[fm][fn][3]);
            }
    }
}

// =====================================================================
// Kernel 2: reduce partials -> score -> argmax -> gather style row.
// =====================================================================
__global__ __launch_bounds__(1024)
void argmax_gather_kernel(const float* __restrict__ style,
                          float* __restrict__ out) {
    const int b   = blockIdx.x;
    const int tid = threadIdx.x;
    const int m   = tid & 255;
    const int q   = tid >> 8;            // 0..3
    const int CPQ = NCTA / 4;            // 38

    float sim = 0.f, n2 = 0.f;
    const int c0 = q * CPQ;
    for (int c = c0; c < c0 + CPQ; ++c) {
        sim += g_psim[(size_t)c * (BQ * MB) + b * MB + m];
        n2  += g_pnorm[(size_t)c * MB + m];
    }

    __shared__ float s_sim[4][256];
    __shared__ float s_n2[4][256];
    s_sim[q][m] = sim;
    s_n2[q][m]  = n2;
    __syncthreads();

    __shared__ float s_val[256];
    __shared__ int   s_idx[256];
    if (q == 0) {
        const float st = s_sim[0][m] + s_sim[1][m] + s_sim[2][m] + s_sim[3][m];
        const float nt = s_n2[0][m]  + s_n2[1][m]  + s_n2[2][m]  + s_n2[3][m];
        const float norm = fmaxf(sqrtf(nt), 1e-12f);
        s_val[m] = st / norm;
        s_idx[m] = m;
    }
    __syncthreads();

    #pragma unroll
    for (int s = 128; s > 0; s >>= 1) {
        if (tid < s) {
            const float v1 = s_val[tid + s], v0 = s_val[tid];
            const int   i1 = s_idx[tid + s], i0 = s_idx[tid];
            if (v1 > v0 || (v1 == v0 && i1 < i0)) {
                s_val[tid] = v1;
                s_idx[tid] = i1;
            }
        }
        __syncthreads();
    }
    const int idx = s_idx[0];

    const float2* src = (const float2*)(style + (size_t)idx * SDIM);
    float2* dst = (float2*)(out + (size_t)b * SDIM);
    dst[tid] = src[tid];
}

extern "C" void kernel_launch(void* const* d_in, const int* in_sizes, int n_in,
                              void* d_out, int out_size) {
    const float* content = (const float*)d_in[0];   // [64, 512, 32, 32]
    const float* bank    = (const float*)d_in[1];   // [256, 524288]
    const float* style   = (const float*)d_in[2];   // [256, 2048]
    float* out = (float*)d_out;                     // [64, 2048]

    cudaFuncSetAttribute(sim_mma_kernel,
                         cudaFuncAttributeMaxDynamicSharedMemorySize, SMEM_TOTAL);

    sim_mma_kernel<<<NCTA, 256, SMEM_TOTAL>>>(content, bank);
    argmax_gather_kernel<<<BQ, 1024>>>(style, out);
}